// round 7
// baseline (speedup 1.0000x reference)
#include <cuda_runtime.h>
#include <cuda_bf16.h>
#include <cstdint>
#include <cstring>

#define BATCH 4096
#define DIM   256
#define NREL  30
#define GS    32          // samples per group (MMA M dim)
#define MAXG  160         // >= 30 + 4096/32
#define NTH   256
#define KC    32          // K rows per pipeline chunk
#define NCHUNKS 8         // DIM / KC
#define AST   40          // A smem row stride (halves): 32 + 8 pad
#define BST   264         // B smem row stride (halves): 256 + 8 pad
#define TST   260         // tT row stride (floats)

#define PREP_CTAS 1185    // CTA 0: grouping; 1..1184: conversion
#define NM4 (NREL * DIM * DIM / 4)
#define NH4 (BATCH * DIM / 4)

// SMEM byte offsets (dynamic smem)
#define OFF_SIDX 0                        // 32 ints
#define OFF_RED  128                      // 128 floats (4 n-warps x 32 rows)
#define OFF_TT   640                      // 32 x 260 floats = 33280
#define OFF_A    33920                    // [2 buf][2 mat][32 s][40 h] *2B = 10240
#define OFF_B    44160                    // [2 buf][2 mat][32 k][264 h]*2B = 67584
#define SMEM_BYTES 111744

// ---- device scratch ----
__device__ int g_grp_rel[MAXG];
__device__ int g_grp_start[MAXG];
__device__ int g_sorted[MAXG * GS];
__device__ int g_ngrp;
__device__ __nv_bfloat16 g_Mb[NREL * DIM * DIM];
__device__ __nv_bfloat16 g_Ms[NREL * DIM * DIM];
__device__ __nv_bfloat16 g_Hb[BATCH * DIM];
__device__ __nv_bfloat16 g_Hs[BATCH * DIM];

// ---- helpers ----
__device__ __forceinline__ uint32_t smem_u32(const void* p) {
    uint32_t a;
    asm("{ .reg .u64 t; cvta.to.shared.u64 t, %1; cvt.u32.u64 %0, t; }" : "=r"(a) : "l"(p));
    return a;
}
__device__ __forceinline__ void cpasync16(uint32_t dst, const void* src) {
    asm volatile("cp.async.cg.shared.global [%0], [%1], 16;" :: "r"(dst), "l"(src));
}
__device__ __forceinline__ void sts16_zero(uint32_t dst) {
    asm volatile("st.shared.v4.b32 [%0], {%1,%1,%1,%1};" :: "r"(dst), "r"(0u) : "memory");
}
__device__ __forceinline__ void ldm_x4(uint32_t* r, uint32_t addr) {
    asm volatile("ldmatrix.sync.aligned.m8n8.x4.shared.b16 {%0,%1,%2,%3}, [%4];"
                 : "=r"(r[0]), "=r"(r[1]), "=r"(r[2]), "=r"(r[3]) : "r"(addr));
}
__device__ __forceinline__ void ldm_x4_t(uint32_t* r, uint32_t addr) {
    asm volatile("ldmatrix.sync.aligned.m8n8.x4.trans.shared.b16 {%0,%1,%2,%3}, [%4];"
                 : "=r"(r[0]), "=r"(r[1]), "=r"(r[2]), "=r"(r[3]) : "r"(addr));
}
__device__ __forceinline__ void mma_bf16(float* c, const uint32_t* a, const uint32_t* b) {
    asm volatile("mma.sync.aligned.m16n8k16.row.col.f32.bf16.bf16.f32 "
                 "{%0,%1,%2,%3}, {%4,%5,%6,%7}, {%8,%9}, {%0,%1,%2,%3};"
                 : "+f"(c[0]), "+f"(c[1]), "+f"(c[2]), "+f"(c[3])
                 : "r"(a[0]), "r"(a[1]), "r"(a[2]), "r"(a[3]), "r"(b[0]), "r"(b[1]));
}
__device__ __forceinline__ uint32_t bf2bits(__nv_bfloat162 v) {
    uint32_t u; memcpy(&u, &v, 4); return u;
}

// ---------------------------------------------------------------------------
// Kernel A (fused prep): CTA 0 groups samples by relation; CTAs 1..N convert
// fp32 -> (big, small) bf16 for M and H with float4 loads / 8B packed stores.
// ---------------------------------------------------------------------------
__global__ __launch_bounds__(NTH)
void prep_kernel(const float* __restrict__ head,
                 const float* __restrict__ relmat,
                 const int* __restrict__ ids32) {
    int tid = threadIdx.x;

    if (blockIdx.x == 0) {
        // ---- grouping (256 threads) ----
        __shared__ int cnt[NREL];
        __shared__ int fill[NREL];
        __shared__ int pad_off[NREL + 1];
        __shared__ int odd_nonzero;

        if (tid < NREL) { cnt[tid] = 0; fill[tid] = 0; }
        if (tid == 0) odd_nonzero = 0;
        __syncthreads();
        for (int i = tid; i < BATCH / 2; i += NTH)
            if (ids32[2 * i + 1] != 0) odd_nonzero = 1;
        __syncthreads();
        const int stride = odd_nonzero ? 1 : 2;   // int32 : int64 low word

        for (int i = tid; i < BATCH; i += NTH) {
            int r = ids32[i * stride];
            if ((unsigned)r < NREL) atomicAdd(&cnt[r], 1);
        }
        __syncthreads();

        if (tid == 0) {
            int off = 0, t = 0;
            for (int r = 0; r < NREL; r++) {
                pad_off[r] = off;
                int ng = (cnt[r] + GS - 1) / GS;
                for (int k = 0; k < ng; k++) {
                    g_grp_rel[t] = r;
                    g_grp_start[t] = off + k * GS;
                    t++;
                }
                off += ng * GS;
            }
            g_ngrp = t;
        }
        __syncthreads();

        for (int i = tid; i < MAXG * GS; i += NTH) g_sorted[i] = -1;
        __syncthreads();

        for (int i = tid; i < BATCH; i += NTH) {
            int r = ids32[i * stride];
            if ((unsigned)r < NREL) {
                int p = pad_off[r] + atomicAdd(&fill[r], 1);
                g_sorted[p] = i;
            }
        }
        return;
    }

    // ---- conversion (1184 CTAs) ----
    int cta = blockIdx.x - 1;
    int nthr = (PREP_CTAS - 1) * NTH;
    int t0 = cta * NTH + tid;

    const float4* M4 = (const float4*)relmat;
    uint2* Mb4 = (uint2*)g_Mb;
    uint2* Ms4 = (uint2*)g_Ms;
    for (int e = t0; e < NM4; e += nthr) {
        float4 v = M4[e];
        __nv_bfloat162 b0 = __float22bfloat162_rn(make_float2(v.x, v.y));
        __nv_bfloat162 b1 = __float22bfloat162_rn(make_float2(v.z, v.w));
        float2 f0 = __bfloat1622float2(b0), f1 = __bfloat1622float2(b1);
        __nv_bfloat162 s0 = __float22bfloat162_rn(make_float2(v.x - f0.x, v.y - f0.y));
        __nv_bfloat162 s1 = __float22bfloat162_rn(make_float2(v.z - f1.x, v.w - f1.y));
        Mb4[e] = make_uint2(bf2bits(b0), bf2bits(b1));
        Ms4[e] = make_uint2(bf2bits(s0), bf2bits(s1));
    }

    const float4* H4 = (const float4*)head;
    uint2* Hb4 = (uint2*)g_Hb;
    uint2* Hs4 = (uint2*)g_Hs;
    for (int e = t0; e < NH4; e += nthr) {
        float4 v = H4[e];
        __nv_bfloat162 b0 = __float22bfloat162_rn(make_float2(v.x, v.y));
        __nv_bfloat162 b1 = __float22bfloat162_rn(make_float2(v.z, v.w));
        float2 f0 = __bfloat1622float2(b0), f1 = __bfloat1622float2(b1);
        __nv_bfloat162 s0 = __float22bfloat162_rn(make_float2(v.x - f0.x, v.y - f0.y));
        __nv_bfloat162 s1 = __float22bfloat162_rn(make_float2(v.z - f1.x, v.w - f1.y));
        Hb4[e] = make_uint2(bf2bits(b0), bf2bits(b1));
        Hs4[e] = make_uint2(bf2bits(s0), bf2bits(s1));
    }
}

// ---------------------------------------------------------------------------
// Kernel B: one CTA per group. Y[32,256] = H*M via 3-pass bf16 mma.sync,
// epilogue folds t and reduces deterministically. 8 warps: 2 m-tiles x 4 n-warps.
// (unchanged from R6 — passed with rel_err 4.5e-6)
// ---------------------------------------------------------------------------
extern __shared__ char smem[];

__device__ __forceinline__ void issue_chunk(
    int kc, int tid, uint32_t sb, const int* s_idx,
    const __nv_bfloat16* MbP, const __nv_bfloat16* MsP) {
    int buf = kc & 1;
    // A: 2 mats x 32 rows x 4 u (16B each) = 256 transfers, one per thread
    {
        int mat = tid >> 7, idx = tid & 127;
        int s = idx >> 2, u = idx & 3;
        int gi = s_idx[s];
        uint32_t dst = sb + OFF_A + (uint32_t)(((buf * 2 + mat) * GS * AST + s * AST + u * 8) * 2);
        if (gi >= 0)
            cpasync16(dst, (mat ? g_Hs : g_Hb) + (size_t)gi * DIM + kc * KC + u * 8);
        else
            sts16_zero(dst);
    }
    // B: 2 mats x 32 k-rows x 32 u = 2048 transfers, 8 per thread
    #pragma unroll
    for (int k = 0; k < 8; k++) {
        int e = tid + k * NTH;
        int mat = e >> 10, idx = e & 1023;
        int kr = idx >> 5, u = idx & 31;
        uint32_t dst = sb + OFF_B + (uint32_t)(((buf * 2 + mat) * KC * BST + kr * BST + u * 8) * 2);
        cpasync16(dst, (mat ? MsP : MbP) + (size_t)(kc * KC + kr) * DIM + u * 8);
    }
    asm volatile("cp.async.commit_group;" ::: "memory");
}

__global__ __launch_bounds__(NTH, 1)
void mma_kernel(const float* __restrict__ tail, float* __restrict__ out) {
    int g = blockIdx.x;
    if (g >= g_ngrp) return;

    int tid = threadIdx.x, wid = tid >> 5, l = tid & 31;
    int mw = wid & 1;          // m-tile (16 rows)
    int nw = wid >> 1;         // n-warp (64 cols)
    uint32_t sb = smem_u32(smem);
    int* s_idx = (int*)(smem + OFF_SIDX);
    float* red = (float*)(smem + OFF_RED);
    float* tT  = (float*)(smem + OFF_TT);

    int r = g_grp_rel[g];
    int start = g_grp_start[g];
    if (tid < GS) s_idx[tid] = g_sorted[start + tid];
    __syncthreads();

    const __nv_bfloat16* MbP = g_Mb + (size_t)r * DIM * DIM;
    const __nv_bfloat16* MsP = g_Ms + (size_t)r * DIM * DIM;

    issue_chunk(0, tid, sb, s_idx, MbP, MsP);
    issue_chunk(1, tid, sb, s_idx, MbP, MsP);

    // t tile (fp32), zero-filled for padded rows; overlaps cp.async flight
    for (int e = tid; e < GS * (DIM / 4); e += NTH) {   // 2048
        int s = e >> 6, cc = e & 63;
        int gi = s_idx[s];
        float4 tv = make_float4(0.f, 0.f, 0.f, 0.f);
        if (gi >= 0) tv = ((const float4*)(tail + (size_t)gi * DIM))[cc];
        *(float4*)(tT + s * TST + cc * 4) = tv;
    }

    float c[8][4];
    #pragma unroll
    for (int nf = 0; nf < 8; nf++)
        #pragma unroll
        for (int k = 0; k < 4; k++) c[nf][k] = 0.f;

    // lane-invariant frag addressing pieces
    uint32_t a_row  = mw * 16 + (l & 15);
    uint32_t a_koff = (uint32_t)((l >> 4) << 3);
    uint32_t b_krow = (uint32_t)(l & 15);
    uint32_t b_ncol = (uint32_t)(nw * 64 + ((l >> 4) << 3));

    for (int kc = 0; kc < NCHUNKS; kc++) {
        if (kc == NCHUNKS - 1)
            asm volatile("cp.async.wait_group 0;" ::: "memory");
        else
            asm volatile("cp.async.wait_group 1;" ::: "memory");
        __syncthreads();

        int buf = kc & 1;
        uint32_t Ab0 = sb + OFF_A + (uint32_t)((buf * 2 + 0) * GS * AST * 2);
        uint32_t Ab1 = sb + OFF_A + (uint32_t)((buf * 2 + 1) * GS * AST * 2);
        uint32_t Bb0 = sb + OFF_B + (uint32_t)((buf * 2 + 0) * KC * BST * 2);
        uint32_t Bb1 = sb + OFF_B + (uint32_t)((buf * 2 + 1) * KC * BST * 2);

        #pragma unroll
        for (int ks = 0; ks < KC / 16; ks++) {
            uint32_t aB[4], aS[4];
            uint32_t ka = ks * 16 + a_koff;
            ldm_x4(aB, Ab0 + (a_row * AST + ka) * 2);
            ldm_x4(aS, Ab1 + (a_row * AST + ka) * 2);
            #pragma unroll
            for (int nt = 0; nt < 4; nt++) {
                uint32_t bB[4], bS[4];
                uint32_t boff = ((ks * 16 + b_krow) * BST + b_ncol + nt * 16) * 2;
                ldm_x4_t(bB, Bb0 + boff);
                ldm_x4_t(bS, Bb1 + boff);
                mma_bf16(c[2 * nt],     aB, bB);
                mma_bf16(c[2 * nt + 1], aB, bB + 2);
                mma_bf16(c[2 * nt],     aB, bS);
                mma_bf16(c[2 * nt + 1], aB, bS + 2);
                mma_bf16(c[2 * nt],     aS, bB);
                mma_bf16(c[2 * nt + 1], aS, bB + 2);
            }
        }
        __syncthreads();
        if (kc + 2 < NCHUNKS) issue_chunk(kc + 2, tid, sb, s_idx, MbP, MsP);
    }

    // ---- epilogue: fold t, quad-reduce, deterministic combine ----
    int q = l & 3, a = l >> 2;
    int row0 = mw * 16 + a, row1 = row0 + 8;
    float p0 = 0.f, p1 = 0.f;
    #pragma unroll
    for (int nf = 0; nf < 8; nf++) {
        int j = nw * 64 + nf * 8 + q * 2;
        p0 += c[nf][0] * tT[row0 * TST + j] + c[nf][1] * tT[row0 * TST + j + 1];
        p1 += c[nf][2] * tT[row1 * TST + j] + c[nf][3] * tT[row1 * TST + j + 1];
    }
    p0 += __shfl_xor_sync(0xFFFFFFFF, p0, 1);
    p0 += __shfl_xor_sync(0xFFFFFFFF, p0, 2);
    p1 += __shfl_xor_sync(0xFFFFFFFF, p1, 1);
    p1 += __shfl_xor_sync(0xFFFFFFFF, p1, 2);
    if (q == 0) {
        red[nw * 32 + row0] = p0;
        red[nw * 32 + row1] = p1;
    }
    __syncthreads();

    if (tid < GS) {
        int gi = s_idx[tid];
        if (gi >= 0)
            out[gi] = red[tid] + red[32 + tid] + red[64 + tid] + red[96 + tid];
    }
}

// ---------------------------------------------------------------------------
// Launch: resolve input slots by element count.
// ---------------------------------------------------------------------------
extern "C" void kernel_launch(void* const* d_in, const int* in_sizes, int n_in,
                              void* d_out, int out_size) {
    const float* head = nullptr;
    const float* tail = nullptr;
    const int*   ids  = nullptr;
    const float* relmat = nullptr;

    for (int i = 0; i < n_in; i++) {
        if (in_sizes[i] == BATCH)                 ids    = (const int*)d_in[i];
        else if (in_sizes[i] == NREL * DIM * DIM) relmat = (const float*)d_in[i];
        else if (in_sizes[i] == BATCH * DIM) {
            if (!head) head = (const float*)d_in[i];
            else       tail = (const float*)d_in[i];
        }
    }
    float* out = (float*)d_out;

    cudaFuncSetAttribute(mma_kernel,
                         cudaFuncAttributeMaxDynamicSharedMemorySize, SMEM_BYTES);

    prep_kernel<<<PREP_CTAS, NTH>>>(head, relmat, ids);
    mma_kernel<<<MAXG, NTH, SMEM_BYTES>>>(tail, out);
}

// round 8
// speedup vs baseline: 1.0056x; 1.0056x over previous
#include <cuda_runtime.h>
#include <cuda_bf16.h>
#include <cstdint>
#include <cstring>

#define BATCH 4096
#define DIM   256
#define NREL  30
#define GS    32          // samples per group (MMA M dim)
#define MAXG  160         // >= 30 + 4096/32
#define NTH   256
#define KC    32          // K rows per pipeline chunk
#define KSPLIT 2          // K halves (CTAs per group)
#define LCHUNKS 4         // chunks per CTA = DIM / KC / KSPLIT
#define AST   40          // A smem row stride (halves): 32 + 8 pad
#define BST   264         // B smem row stride (halves): 256 + 8 pad
#define TST   260         // tT row stride (floats)

#define PREP_CTAS 1185    // CTA 0: grouping + out zero; 1..1184: conversion
#define NM4 (NREL * DIM * DIM / 4)
#define NH4 (BATCH * DIM / 4)

// SMEM byte offsets (dynamic smem)
#define OFF_SIDX 0                        // 32 ints
#define OFF_RED  128                      // 128 floats (4 n-warps x 32 rows)
#define OFF_TT   640                      // 32 x 260 floats = 33280
#define OFF_A    33920                    // [2 buf][2 mat][32 s][40 h] *2B = 10240
#define OFF_B    44160                    // [2 buf][2 mat][32 k][264 h]*2B = 67584
#define SMEM_BYTES 111744                 // x2 CTAs = 223488 <= 228KB/SM

// ---- device scratch ----
__device__ int g_grp_rel[MAXG];
__device__ int g_grp_start[MAXG];
__device__ int g_sorted[MAXG * GS];
__device__ int g_ngrp;
__device__ __nv_bfloat16 g_Mb[NREL * DIM * DIM];
__device__ __nv_bfloat16 g_Ms[NREL * DIM * DIM];
__device__ __nv_bfloat16 g_Hb[BATCH * DIM];
__device__ __nv_bfloat16 g_Hs[BATCH * DIM];

// ---- helpers ----
__device__ __forceinline__ uint32_t smem_u32(const void* p) {
    uint32_t a;
    asm("{ .reg .u64 t; cvta.to.shared.u64 t, %1; cvt.u32.u64 %0, t; }" : "=r"(a) : "l"(p));
    return a;
}
__device__ __forceinline__ void cpasync16(uint32_t dst, const void* src) {
    asm volatile("cp.async.cg.shared.global [%0], [%1], 16;" :: "r"(dst), "l"(src));
}
__device__ __forceinline__ void sts16_zero(uint32_t dst) {
    asm volatile("st.shared.v4.b32 [%0], {%1,%1,%1,%1};" :: "r"(dst), "r"(0u) : "memory");
}
__device__ __forceinline__ void ldm_x4(uint32_t* r, uint32_t addr) {
    asm volatile("ldmatrix.sync.aligned.m8n8.x4.shared.b16 {%0,%1,%2,%3}, [%4];"
                 : "=r"(r[0]), "=r"(r[1]), "=r"(r[2]), "=r"(r[3]) : "r"(addr));
}
__device__ __forceinline__ void ldm_x4_t(uint32_t* r, uint32_t addr) {
    asm volatile("ldmatrix.sync.aligned.m8n8.x4.trans.shared.b16 {%0,%1,%2,%3}, [%4];"
                 : "=r"(r[0]), "=r"(r[1]), "=r"(r[2]), "=r"(r[3]) : "r"(addr));
}
__device__ __forceinline__ void mma_bf16(float* c, const uint32_t* a, const uint32_t* b) {
    asm volatile("mma.sync.aligned.m16n8k16.row.col.f32.bf16.bf16.f32 "
                 "{%0,%1,%2,%3}, {%4,%5,%6,%7}, {%8,%9}, {%0,%1,%2,%3};"
                 : "+f"(c[0]), "+f"(c[1]), "+f"(c[2]), "+f"(c[3])
                 : "r"(a[0]), "r"(a[1]), "r"(a[2]), "r"(a[3]), "r"(b[0]), "r"(b[1]));
}
__device__ __forceinline__ uint32_t bf2bits(__nv_bfloat162 v) {
    uint32_t u; memcpy(&u, &v, 4); return u;
}

// ---------------------------------------------------------------------------
// Kernel A (fused prep): CTA 0 groups samples by relation + zeroes out;
// CTAs 1..N convert fp32 -> (big, small) bf16 for M and H.
// ---------------------------------------------------------------------------
__global__ __launch_bounds__(NTH)
void prep_kernel(const float* __restrict__ head,
                 const float* __restrict__ relmat,
                 const int* __restrict__ ids32,
                 float* __restrict__ out) {
    int tid = threadIdx.x;

    if (blockIdx.x == 0) {
        __shared__ int cnt[NREL];
        __shared__ int fill[NREL];
        __shared__ int pad_off[NREL + 1];
        __shared__ int odd_nonzero;

        for (int i = tid; i < BATCH; i += NTH) out[i] = 0.0f;

        if (tid < NREL) { cnt[tid] = 0; fill[tid] = 0; }
        if (tid == 0) odd_nonzero = 0;
        __syncthreads();
        for (int i = tid; i < BATCH / 2; i += NTH)
            if (ids32[2 * i + 1] != 0) odd_nonzero = 1;
        __syncthreads();
        const int stride = odd_nonzero ? 1 : 2;   // int32 : int64 low word

        for (int i = tid; i < BATCH; i += NTH) {
            int r = ids32[i * stride];
            if ((unsigned)r < NREL) atomicAdd(&cnt[r], 1);
        }
        __syncthreads();

        if (tid == 0) {
            int off = 0, t = 0;
            for (int r = 0; r < NREL; r++) {
                pad_off[r] = off;
                int ng = (cnt[r] + GS - 1) / GS;
                for (int k = 0; k < ng; k++) {
                    g_grp_rel[t] = r;
                    g_grp_start[t] = off + k * GS;
                    t++;
                }
                off += ng * GS;
            }
            g_ngrp = t;
        }
        __syncthreads();

        for (int i = tid; i < MAXG * GS; i += NTH) g_sorted[i] = -1;
        __syncthreads();

        for (int i = tid; i < BATCH; i += NTH) {
            int r = ids32[i * stride];
            if ((unsigned)r < NREL) {
                int p = pad_off[r] + atomicAdd(&fill[r], 1);
                g_sorted[p] = i;
            }
        }
        return;
    }

    int cta = blockIdx.x - 1;
    int nthr = (PREP_CTAS - 1) * NTH;
    int t0 = cta * NTH + tid;

    const float4* M4 = (const float4*)relmat;
    uint2* Mb4 = (uint2*)g_Mb;
    uint2* Ms4 = (uint2*)g_Ms;
    for (int e = t0; e < NM4; e += nthr) {
        float4 v = M4[e];
        __nv_bfloat162 b0 = __float22bfloat162_rn(make_float2(v.x, v.y));
        __nv_bfloat162 b1 = __float22bfloat162_rn(make_float2(v.z, v.w));
        float2 f0 = __bfloat1622float2(b0), f1 = __bfloat1622float2(b1);
        __nv_bfloat162 s0 = __float22bfloat162_rn(make_float2(v.x - f0.x, v.y - f0.y));
        __nv_bfloat162 s1 = __float22bfloat162_rn(make_float2(v.z - f1.x, v.w - f1.y));
        Mb4[e] = make_uint2(bf2bits(b0), bf2bits(b1));
        Ms4[e] = make_uint2(bf2bits(s0), bf2bits(s1));
    }

    const float4* H4 = (const float4*)head;
    uint2* Hb4 = (uint2*)g_Hb;
    uint2* Hs4 = (uint2*)g_Hs;
    for (int e = t0; e < NH4; e += nthr) {
        float4 v = H4[e];
        __nv_bfloat162 b0 = __float22bfloat162_rn(make_float2(v.x, v.y));
        __nv_bfloat162 b1 = __float22bfloat162_rn(make_float2(v.z, v.w));
        float2 f0 = __bfloat1622float2(b0), f1 = __bfloat1622float2(b1);
        __nv_bfloat162 s0 = __float22bfloat162_rn(make_float2(v.x - f0.x, v.y - f0.y));
        __nv_bfloat162 s1 = __float22bfloat162_rn(make_float2(v.z - f1.x, v.w - f1.y));
        Hb4[e] = make_uint2(bf2bits(b0), bf2bits(b1));
        Hs4[e] = make_uint2(bf2bits(s0), bf2bits(s1));
    }
}

// ---------------------------------------------------------------------------
// Kernel B: CTA = (group, k-half). Partial Y[32,256] over K=128 via 3-pass
// bf16 mma.sync; epilogue folds t and atomicAdds a partial score (2 partials
// per sample, commutative -> deterministic). 2 CTAs/SM -> 16 warps/SM.
// ---------------------------------------------------------------------------
extern __shared__ char smem[];

__device__ __forceinline__ void issue_chunk(
    int kcg, int buf, int tid, uint32_t sb, const int* s_idx,
    const __nv_bfloat16* MbP, const __nv_bfloat16* MsP) {
    // A: 2 mats x 32 rows x 4 u (16B each) = 256 transfers, one per thread
    {
        int mat = tid >> 7, idx = tid & 127;
        int s = idx >> 2, u = idx & 3;
        int gi = s_idx[s];
        uint32_t dst = sb + OFF_A + (uint32_t)(((buf * 2 + mat) * GS * AST + s * AST + u * 8) * 2);
        if (gi >= 0)
            cpasync16(dst, (mat ? g_Hs : g_Hb) + (size_t)gi * DIM + kcg * KC + u * 8);
        else
            sts16_zero(dst);
    }
    // B: 2 mats x 32 k-rows x 32 u = 2048 transfers, 8 per thread
    #pragma unroll
    for (int k = 0; k < 8; k++) {
        int e = tid + k * NTH;
        int mat = e >> 10, idx = e & 1023;
        int kr = idx >> 5, u = idx & 31;
        uint32_t dst = sb + OFF_B + (uint32_t)(((buf * 2 + mat) * KC * BST + kr * BST + u * 8) * 2);
        cpasync16(dst, (mat ? MsP : MbP) + (size_t)(kcg * KC + kr) * DIM + u * 8);
    }
    asm volatile("cp.async.commit_group;" ::: "memory");
}

__global__ __launch_bounds__(NTH)
void mma_kernel(const float* __restrict__ tail, float* __restrict__ out) {
    int g  = blockIdx.x >> 1;
    int kh = blockIdx.x & 1;
    if (g >= g_ngrp) return;

    int tid = threadIdx.x, wid = tid >> 5, l = tid & 31;
    int mw = wid & 1;          // m-tile (16 rows)
    int nw = wid >> 1;         // n-warp (64 cols)
    uint32_t sb = smem_u32(smem);
    int* s_idx = (int*)(smem + OFF_SIDX);
    float* red = (float*)(smem + OFF_RED);
    float* tT  = (float*)(smem + OFF_TT);

    int r = g_grp_rel[g];
    int start = g_grp_start[g];
    if (tid < GS) s_idx[tid] = g_sorted[start + tid];
    __syncthreads();

    const __nv_bfloat16* MbP = g_Mb + (size_t)r * DIM * DIM;
    const __nv_bfloat16* MsP = g_Ms + (size_t)r * DIM * DIM;
    const int kc0 = kh * LCHUNKS;   // this CTA's global chunk base

    issue_chunk(kc0 + 0, 0, tid, sb, s_idx, MbP, MsP);
    issue_chunk(kc0 + 1, 1, tid, sb, s_idx, MbP, MsP);

    // t tile (fp32), zero-filled for padded rows; overlaps cp.async flight
    for (int e = tid; e < GS * (DIM / 4); e += NTH) {   // 2048
        int s = e >> 6, cc = e & 63;
        int gi = s_idx[s];
        float4 tv = make_float4(0.f, 0.f, 0.f, 0.f);
        if (gi >= 0) tv = ((const float4*)(tail + (size_t)gi * DIM))[cc];
        *(float4*)(tT + s * TST + cc * 4) = tv;
    }

    float c[8][4];
    #pragma unroll
    for (int nf = 0; nf < 8; nf++)
        #pragma unroll
        for (int k = 0; k < 4; k++) c[nf][k] = 0.f;

    uint32_t a_row  = mw * 16 + (l & 15);
    uint32_t a_koff = (uint32_t)((l >> 4) << 3);
    uint32_t b_krow = (uint32_t)(l & 15);
    uint32_t b_ncol = (uint32_t)(nw * 64 + ((l >> 4) << 3));

    for (int kc = 0; kc < LCHUNKS; kc++) {
        if (kc == LCHUNKS - 1)
            asm volatile("cp.async.wait_group 0;" ::: "memory");
        else
            asm volatile("cp.async.wait_group 1;" ::: "memory");
        __syncthreads();

        int buf = kc & 1;
        uint32_t Ab0 = sb + OFF_A + (uint32_t)((buf * 2 + 0) * GS * AST * 2);
        uint32_t Ab1 = sb + OFF_A + (uint32_t)((buf * 2 + 1) * GS * AST * 2);
        uint32_t Bb0 = sb + OFF_B + (uint32_t)((buf * 2 + 0) * KC * BST * 2);
        uint32_t Bb1 = sb + OFF_B + (uint32_t)((buf * 2 + 1) * KC * BST * 2);

        #pragma unroll
        for (int ks = 0; ks < KC / 16; ks++) {
            uint32_t aB[4], aS[4];
            uint32_t ka = ks * 16 + a_koff;
            ldm_x4(aB, Ab0 + (a_row * AST + ka) * 2);
            ldm_x4(aS, Ab1 + (a_row * AST + ka) * 2);
            #pragma unroll
            for (int nt = 0; nt < 4; nt++) {
                uint32_t bB[4], bS[4];
                uint32_t boff = ((ks * 16 + b_krow) * BST + b_ncol + nt * 16) * 2;
                ldm_x4_t(bB, Bb0 + boff);
                ldm_x4_t(bS, Bb1 + boff);
                mma_bf16(c[2 * nt],     aB, bB);
                mma_bf16(c[2 * nt + 1], aB, bB + 2);
                mma_bf16(c[2 * nt],     aB, bS);
                mma_bf16(c[2 * nt + 1], aB, bS + 2);
                mma_bf16(c[2 * nt],     aS, bB);
                mma_bf16(c[2 * nt + 1], aS, bB + 2);
            }
        }
        __syncthreads();
        if (kc + 2 < LCHUNKS)
            issue_chunk(kc0 + kc + 2, kc & 1, tid, sb, s_idx, MbP, MsP);
    }

    // ---- epilogue: fold t, quad-reduce, deterministic combine ----
    int q = l & 3, a = l >> 2;
    int row0 = mw * 16 + a, row1 = row0 + 8;
    float p0 = 0.f, p1 = 0.f;
    #pragma unroll
    for (int nf = 0; nf < 8; nf++) {
        int j = nw * 64 + nf * 8 + q * 2;
        p0 += c[nf][0] * tT[row0 * TST + j] + c[nf][1] * tT[row0 * TST + j + 1];
        p1 += c[nf][2] * tT[row1 * TST + j] + c[nf][3] * tT[row1 * TST + j + 1];
    }
    p0 += __shfl_xor_sync(0xFFFFFFFF, p0, 1);
    p0 += __shfl_xor_sync(0xFFFFFFFF, p0, 2);
    p1 += __shfl_xor_sync(0xFFFFFFFF, p1, 1);
    p1 += __shfl_xor_sync(0xFFFFFFFF, p1, 2);
    if (q == 0) {
        red[nw * 32 + row0] = p0;
        red[nw * 32 + row1] = p1;
    }
    __syncthreads();

    if (tid < GS) {
        int gi = s_idx[tid];
        if (gi >= 0)
            atomicAdd(&out[gi], red[tid] + red[32 + tid] + red[64 + tid] + red[96 + tid]);
    }
}

// ---------------------------------------------------------------------------
// Launch: resolve input slots by element count.
// ---------------------------------------------------------------------------
extern "C" void kernel_launch(void* const* d_in, const int* in_sizes, int n_in,
                              void* d_out, int out_size) {
    const float* head = nullptr;
    const float* tail = nullptr;
    const int*   ids  = nullptr;
    const float* relmat = nullptr;

    for (int i = 0; i < n_in; i++) {
        if (in_sizes[i] == BATCH)                 ids    = (const int*)d_in[i];
        else if (in_sizes[i] == NREL * DIM * DIM) relmat = (const float*)d_in[i];
        else if (in_sizes[i] == BATCH * DIM) {
            if (!head) head = (const float*)d_in[i];
            else       tail = (const float*)d_in[i];
        }
    }
    float* out = (float*)d_out;

    cudaFuncSetAttribute(mma_kernel,
                         cudaFuncAttributeMaxDynamicSharedMemorySize, SMEM_BYTES);

    prep_kernel<<<PREP_CTAS, NTH>>>(head, relmat, ids, out);
    mma_kernel<<<MAXG * KSPLIT, NTH, SMEM_BYTES>>>(tail, out);
}

// round 10
// speedup vs baseline: 1.2762x; 1.2691x over previous
#include <cuda_runtime.h>
#include <cuda_bf16.h>
#include <cstdint>
#include <cstring>

#define BATCH 4096
#define DIM   256
#define NREL  30
#define GS    32          // samples per group (MMA M dim)
#define MAXG  160         // >= 30 + 4096/32
#define NTH   256
#define KC    32          // K rows per chunk
#define KSPLIT 2          // K halves (CTAs per group)
#define LCHUNKS 4         // chunks per CTA
#define AST   40          // A bf16 tile row stride (halves)
#define BST   264         // B bf16 tile row stride (halves)
#define TST   260         // tT row stride (floats)

// SMEM byte offsets
#define OFF_SIDX  0                      // 32 ints (128B)
#define OFF_RED   128                    // 128 floats (512B)
#define OFF_ATILE 640                    // [2 mat][32][40] halves = 5120B
#define OFF_BTILE 5760                   // [2 mat][32][264] halves = 33792B
#define OFF_STAGE 39552                  // [2 buf][32][256] fp32 = 65536B (tT reuse at epilogue)
#define SMEM_BYTES 105088                // x2 CTAs = 210176 <= 228KB/SM

// ---- device scratch ----
__device__ int g_grp_rel[MAXG];
__device__ int g_grp_start[MAXG];
__device__ int g_sorted[MAXG * GS];
__device__ int g_ngrp;

// ---- helpers ----
__device__ __forceinline__ uint32_t smem_u32(const void* p) {
    uint32_t a;
    asm("{ .reg .u64 t; cvta.to.shared.u64 t, %1; cvt.u32.u64 %0, t; }" : "=r"(a) : "l"(p));
    return a;
}
__device__ __forceinline__ void cpasync16(uint32_t dst, const void* src) {
    asm volatile("cp.async.cg.shared.global [%0], [%1], 16;" :: "r"(dst), "l"(src));
}
__device__ __forceinline__ void ldm_x4(uint32_t* r, uint32_t addr) {
    asm volatile("ldmatrix.sync.aligned.m8n8.x4.shared.b16 {%0,%1,%2,%3}, [%4];"
                 : "=r"(r[0]), "=r"(r[1]), "=r"(r[2]), "=r"(r[3]) : "r"(addr));
}
__device__ __forceinline__ void ldm_x4_t(uint32_t* r, uint32_t addr) {
    asm volatile("ldmatrix.sync.aligned.m8n8.x4.trans.shared.b16 {%0,%1,%2,%3}, [%4];"
                 : "=r"(r[0]), "=r"(r[1]), "=r"(r[2]), "=r"(r[3]) : "r"(addr));
}
__device__ __forceinline__ void mma_bf16(float* c, const uint32_t* a, const uint32_t* b) {
    asm volatile("mma.sync.aligned.m16n8k16.row.col.f32.bf16.bf16.f32 "
                 "{%0,%1,%2,%3}, {%4,%5,%6,%7}, {%8,%9}, {%0,%1,%2,%3};"
                 : "+f"(c[0]), "+f"(c[1]), "+f"(c[2]), "+f"(c[3])
                 : "r"(a[0]), "r"(a[1]), "r"(a[2]), "r"(a[3]), "r"(b[0]), "r"(b[1]));
}
__device__ __forceinline__ void sts8(uint32_t addr, uint32_t lo, uint32_t hi) {
    asm volatile("st.shared.v2.b32 [%0], {%1,%2};" :: "r"(addr), "r"(lo), "r"(hi) : "memory");
}
__device__ __forceinline__ uint32_t bf2bits(__nv_bfloat162 v) {
    uint32_t u; memcpy(&u, &v, 4); return u;
}
// split float4 into big/small bf16x2 pairs (bit patterns)
__device__ __forceinline__ void split4(float4 v, uint32_t& b0, uint32_t& b1,
                                       uint32_t& s0, uint32_t& s1) {
    __nv_bfloat162 bb0 = __float22bfloat162_rn(make_float2(v.x, v.y));
    __nv_bfloat162 bb1 = __float22bfloat162_rn(make_float2(v.z, v.w));
    float2 f0 = __bfloat1622float2(bb0), f1 = __bfloat1622float2(bb1);
    __nv_bfloat162 ss0 = __float22bfloat162_rn(make_float2(v.x - f0.x, v.y - f0.y));
    __nv_bfloat162 ss1 = __float22bfloat162_rn(make_float2(v.z - f1.x, v.w - f1.y));
    b0 = bf2bits(bb0); b1 = bf2bits(bb1); s0 = bf2bits(ss0); s1 = bf2bits(ss1);
}

// ---------------------------------------------------------------------------
// Kernel 1: grouping (1 CTA, 1024 thr) + zero out. ids int32/int64-robust.
// ---------------------------------------------------------------------------
__global__ void group_kernel(const int* __restrict__ ids32, float* __restrict__ out) {
    __shared__ int cnt[NREL];
    __shared__ int fill[NREL];
    __shared__ int pad_off[NREL + 1];
    __shared__ int odd_nonzero;
    int tid = threadIdx.x;

    for (int i = tid; i < BATCH; i += 1024) out[i] = 0.0f;

    if (tid < NREL) { cnt[tid] = 0; fill[tid] = 0; }
    if (tid == 0) odd_nonzero = 0;
    __syncthreads();
    for (int i = tid; i < BATCH / 2; i += 1024)
        if (ids32[2 * i + 1] != 0) odd_nonzero = 1;
    __syncthreads();
    const int stride = odd_nonzero ? 1 : 2;   // int32 : int64 low word

    for (int i = tid; i < BATCH; i += 1024) {
        int r = ids32[i * stride];
        if ((unsigned)r < NREL) atomicAdd(&cnt[r], 1);
    }
    __syncthreads();

    if (tid == 0) {
        int off = 0, t = 0;
        for (int r = 0; r < NREL; r++) {
            pad_off[r] = off;
            int ng = (cnt[r] + GS - 1) / GS;
            for (int k = 0; k < ng; k++) {
                g_grp_rel[t] = r;
                g_grp_start[t] = off + k * GS;
                t++;
            }
            off += ng * GS;
        }
        g_ngrp = t;
    }
    __syncthreads();

    for (int i = tid; i < MAXG * GS; i += 1024) g_sorted[i] = -1;
    __syncthreads();

    for (int i = tid; i < BATCH; i += 1024) {
        int r = ids32[i * stride];
        if ((unsigned)r < NREL) {
            int p = pad_off[r] + atomicAdd(&fill[r], 1);
            g_sorted[p] = i;
        }
    }
}

// ---------------------------------------------------------------------------
// Kernel 2 (fully fused): CTA = (group, k-half). Converts fp32 M/H to
// big/small bf16 in-kernel (zero extra global traffic), 3-pass mma.sync,
// epilogue folds t and atomicAdds partials (2 per sample, deterministic).
// ---------------------------------------------------------------------------
extern __shared__ char smem[];

__global__ __launch_bounds__(NTH, 2)
void mma_kernel(const float* __restrict__ head,
                const float* __restrict__ tail,
                const float* __restrict__ relmat,
                float* __restrict__ out) {
    int g  = blockIdx.x >> 1;
    int kh = blockIdx.x & 1;
    if (g >= g_ngrp) return;

    int tid = threadIdx.x, wid = tid >> 5, l = tid & 31;
    int mw = wid & 1;          // m-tile (16 rows)
    int nw = wid >> 1;         // n-warp (64 cols)
    uint32_t sb = smem_u32(smem);
    int* s_idx = (int*)(smem + OFF_SIDX);
    float* red = (float*)(smem + OFF_RED);

    int r = g_grp_rel[g];
    int start = g_grp_start[g];
    if (tid < GS) s_idx[tid] = g_sorted[start + tid];
    __syncthreads();

    const float* Mf = relmat + (size_t)r * DIM * DIM + (size_t)kh * (DIM / 2) * DIM;
    const int kbase = kh * (DIM / 2);    // this CTA's K offset into H

    // Preload t into registers (latency hidden under whole mainloop)
    float4 treg[8];
    #pragma unroll
    for (int k = 0; k < 8; k++) {
        int e = tid + k * NTH;
        int s = e >> 6, cc = e & 63;
        int gi = s_idx[s];
        treg[k] = make_float4(0.f, 0.f, 0.f, 0.f);
        if (gi >= 0) treg[k] = ((const float4*)(tail + (size_t)gi * DIM))[cc];
    }

    // B fp32 staging issue
    auto issueB = [&](int kc, int buf) {
        const float* src = Mf + (size_t)kc * KC * DIM;
        #pragma unroll
        for (int k = 0; k < 8; k++) {
            int e = tid + k * NTH;                       // < 2048 float4
            cpasync16(sb + OFF_STAGE + buf * 32768 + e * 16, src + e * 4);
        }
        asm volatile("cp.async.commit_group;" ::: "memory");
    };
    issueB(0, 0);
    issueB(1, 1);

    float c[8][4];
    #pragma unroll
    for (int nf = 0; nf < 8; nf++)
        #pragma unroll
        for (int k = 0; k < 4; k++) c[nf][k] = 0.f;

    uint32_t a_row  = mw * 16 + (l & 15);
    uint32_t a_koff = (uint32_t)((l >> 4) << 3);
    uint32_t b_krow = (uint32_t)(l & 15);
    uint32_t b_ncol = (uint32_t)(nw * 64 + ((l >> 4) << 3));

    const int As = tid >> 3, Au = tid & 7;   // A load mapping: sample, float4-col
    const int gia = s_idx[As];

    for (int kc = 0; kc < LCHUNKS; kc++) {
        // A fp32 for this chunk (1 float4/thread)
        float4 av = make_float4(0.f, 0.f, 0.f, 0.f);
        if (gia >= 0)
            av = *(const float4*)(head + (size_t)gia * DIM + kbase + kc * KC + Au * 4);

        if (kc == LCHUNKS - 1)
            asm volatile("cp.async.wait_group 0;" ::: "memory");
        else
            asm volatile("cp.async.wait_group 1;" ::: "memory");
        __syncthreads();   // staging[kc&1] ready; prev compute done (tiles free)

        // ---- convert B: staging fp32 -> big/small bf16 tiles ----
        const float4* st4 = (const float4*)(smem + OFF_STAGE + (kc & 1) * 32768);
        #pragma unroll
        for (int k = 0; k < 8; k++) {
            int e = tid + k * NTH;
            int kr = e >> 6, c4 = e & 63;
            uint32_t b0, b1, s0, s1;
            split4(st4[e], b0, b1, s0, s1);
            uint32_t addr = sb + OFF_BTILE + (uint32_t)(kr * (BST * 2) + c4 * 8);
            sts8(addr, b0, b1);
            sts8(addr + 16896, s0, s1);
        }
        // ---- convert A ----
        {
            uint32_t b0, b1, s0, s1;
            split4(av, b0, b1, s0, s1);
            uint32_t addr = sb + OFF_ATILE + (uint32_t)(As * (AST * 2) + Au * 8);
            sts8(addr, b0, b1);
            sts8(addr + 2560, s0, s1);
        }
        __syncthreads();   // tiles ready; staging[kc&1] free
        if (kc + 2 < LCHUNKS) issueB(kc + 2, kc & 1);

        // ---- compute (identical structure to R8) ----
        uint32_t Ab0 = sb + OFF_ATILE;
        uint32_t Ab1 = sb + OFF_ATILE + 2560;
        uint32_t Bb0 = sb + OFF_BTILE;
        uint32_t Bb1 = sb + OFF_BTILE + 16896;

        #pragma unroll
        for (int ks = 0; ks < KC / 16; ks++) {
            uint32_t aB[4], aS[4];
            uint32_t ka = ks * 16 + a_koff;
            ldm_x4(aB, Ab0 + (a_row * AST + ka) * 2);
            ldm_x4(aS, Ab1 + (a_row * AST + ka) * 2);
            #pragma unroll
            for (int nt = 0; nt < 4; nt++) {
                uint32_t bB[4], bS[4];
                uint32_t boff = ((ks * 16 + b_krow) * BST + b_ncol + nt * 16) * 2;
                ldm_x4_t(bB, Bb0 + boff);
                ldm_x4_t(bS, Bb1 + boff);
                mma_bf16(c[2 * nt],     aB, bB);
                mma_bf16(c[2 * nt + 1], aB, bB + 2);
                mma_bf16(c[2 * nt],     aB, bS);
                mma_bf16(c[2 * nt + 1], aB, bS + 2);
                mma_bf16(c[2 * nt],     aS, bB);
                mma_bf16(c[2 * nt + 1], aS, bB + 2);
            }
        }
    }

    // ---- epilogue: spill t regs to SMEM (staging reuse), fold, reduce ----
    float* tT = (float*)(smem + OFF_STAGE);
    #pragma unroll
    for (int k = 0; k < 8; k++) {
        int e = tid + k * NTH;
        int s = e >> 6, cc = e & 63;
        *(float4*)(tT + s * TST + cc * 4) = treg[k];
    }
    __syncthreads();

    int q = l & 3, a = l >> 2;
    int row0 = mw * 16 + a, row1 = row0 + 8;
    float p0 = 0.f, p1 = 0.f;
    #pragma unroll
    for (int nf = 0; nf < 8; nf++) {
        int j = nw * 64 + nf * 8 + q * 2;
        p0 += c[nf][0] * tT[row0 * TST + j] + c[nf][1] * tT[row0 * TST + j + 1];
        p1 += c[nf][2] * tT[row1 * TST + j] + c[nf][3] * tT[row1 * TST + j + 1];
    }
    p0 += __shfl_xor_sync(0xFFFFFFFF, p0, 1);
    p0 += __shfl_xor_sync(0xFFFFFFFF, p0, 2);
    p1 += __shfl_xor_sync(0xFFFFFFFF, p1, 1);
    p1 += __shfl_xor_sync(0xFFFFFFFF, p1, 2);
    if (q == 0) {
        red[nw * 32 + row0] = p0;
        red[nw * 32 + row1] = p1;
    }
    __syncthreads();

    if (tid < GS) {
        int gi = s_idx[tid];
        if (gi >= 0)
            atomicAdd(&out[gi], red[tid] + red[32 + tid] + red[64 + tid] + red[96 + tid]);
    }
}

// ---------------------------------------------------------------------------
// Launch: resolve input slots by element count.
// ---------------------------------------------------------------------------
extern "C" void kernel_launch(void* const* d_in, const int* in_sizes, int n_in,
                              void* d_out, int out_size) {
    const float* head = nullptr;
    const float* tail = nullptr;
    const int*   ids  = nullptr;
    const float* relmat = nullptr;

    for (int i = 0; i < n_in; i++) {
        if (in_sizes[i] == BATCH)                 ids    = (const int*)d_in[i];
        else if (in_sizes[i] == NREL * DIM * DIM) relmat = (const float*)d_in[i];
        else if (in_sizes[i] == BATCH * DIM) {
            if (!head) head = (const float*)d_in[i];
            else       tail = (const float*)d_in[i];
        }
    }
    float* out = (float*)d_out;

    cudaFuncSetAttribute(mma_kernel,
                         cudaFuncAttributeMaxDynamicSharedMemorySize, SMEM_BYTES);

    group_kernel<<<1, 1024>>>(ids, out);
    mma_kernel<<<MAXG * KSPLIT, NTH, SMEM_BYTES>>>(head, tail, relmat, out);
}